// round 5
// baseline (speedup 1.0000x reference)
#include <cuda_runtime.h>

// Problem constants
#define IN_DIM  8192
#define OUT_DIM 8192

// Partial-kernel tiling: 128 threads x float2 = 256 cols/block
#define P_THREADS 128
#define VEC 2
#define COLS_PER_BLOCK (P_THREADS * VEC)            // 256
#define N_STRIPES      (OUT_DIM / COLS_PER_BLOCK)   // 32
#define N_ROW_CHUNKS   32
#define ROWS_PER_CHUNK (IN_DIM / N_ROW_CHUNKS)      // 256

// Scratch for partial sums: [chunk][col]  (2 MB total)
__device__ float g_s1[N_ROW_CHUNKS * OUT_DIM];
__device__ float g_s2[N_ROW_CHUNKS * OUT_DIM];

__global__ __launch_bounds__(P_THREADS)
void ibp_partial_kernel(const float* __restrict__ l,
                        const float* __restrict__ u,
                        const float* __restrict__ w) {
    __shared__ float sc[ROWS_PER_CHUNK];
    __shared__ float sr[ROWS_PER_CHUNK];

    const int col0 = blockIdx.x * COLS_PER_BLOCK + threadIdx.x * VEC;
    const int row0 = blockIdx.y * ROWS_PER_CHUNK;

    for (int i = threadIdx.x; i < ROWS_PER_CHUNK; i += P_THREADS) {
        float lv = l[row0 + i];
        float uv = u[row0 + i];
        sc[i] = 0.5f * (lv + uv);
        sr[i] = 0.5f * (uv - lv);
    }
    __syncthreads();

    float s1x = 0.f, s1y = 0.f;
    float s2x = 0.f, s2y = 0.f;

    const float2* __restrict__ wp =
        reinterpret_cast<const float2*>(w + (size_t)row0 * OUT_DIM + col0);
    const size_t rstride = OUT_DIM / 2;

    #pragma unroll 16
    for (int i = 0; i < ROWS_PER_CHUNK; i++) {
        float2 wv = __ldcs(&wp[(size_t)i * rstride]);   // stream, evict-first
        float c = sc[i];
        float r = sr[i];
        s1x = fmaf(c, wv.x, s1x);
        s1y = fmaf(c, wv.y, s1y);
        s2x = fmaf(r, fabsf(wv.x), s2x);
        s2y = fmaf(r, fabsf(wv.y), s2y);
    }

    const size_t base = (size_t)blockIdx.y * OUT_DIM + col0;
    *reinterpret_cast<float2*>(&g_s1[base]) = make_float2(s1x, s1y);
    *reinterpret_cast<float2*>(&g_s2[base]) = make_float2(s2x, s2y);
}

// Reduce: grid 256 blocks x 256 threads, single pass over 2 MB.
// Block covers 8 float4-cols (32 floats) x 32 chunk-groups; each group loads
// exactly 1 chunk; smem tree-reduce 32 -> 1 across groups.
#define R_THREADS 256
#define R_COLS4   8                                   // float4 cols per block
#define R_GROUPS  32

__global__ __launch_bounds__(R_THREADS)
void ibp_reduce_kernel(const float* __restrict__ bias,
                       float* __restrict__ out) {
    __shared__ float4 sm1[R_GROUPS][R_COLS4];
    __shared__ float4 sm2[R_GROUPS][R_COLS4];

    const int tx  = threadIdx.x & (R_COLS4 - 1);   // float4 col within block
    const int grp = threadIdx.x / R_COLS4;         // chunk (0..31)
    const int col4 = blockIdx.x * R_COLS4 + tx;    // float4 index in [0, 2048)

    const float4* p1 = reinterpret_cast<const float4*>(g_s1);
    const float4* p2 = reinterpret_cast<const float4*>(g_s2);
    const size_t cstride = OUT_DIM / 4;            // float4 stride per chunk

    float4 a1 = p1[(size_t)grp * cstride + col4];
    float4 a2 = p2[(size_t)grp * cstride + col4];
    sm1[grp][tx] = a1;
    sm2[grp][tx] = a2;
    __syncthreads();

    // tree reduce across chunks: 32 -> 16 -> 8 -> 4 -> 2 -> 1
    #pragma unroll
    for (int s = R_GROUPS / 2; s >= 1; s >>= 1) {
        if (grp < s) {
            float4 b1 = sm1[grp + s][tx];
            float4 b2 = sm2[grp + s][tx];
            a1.x += b1.x; a1.y += b1.y; a1.z += b1.z; a1.w += b1.w;
            a2.x += b2.x; a2.y += b2.y; a2.z += b2.z; a2.w += b2.w;
            sm1[grp][tx] = a1;
            sm2[grp][tx] = a2;
        }
        __syncthreads();
    }

    if (grp == 0) {
        float4 b = reinterpret_cast<const float4*>(bias)[col4];
        float4 lo, hi;
        lo.x = a1.x - a2.x + b.x;  hi.x = a1.x + a2.x + b.x;
        lo.y = a1.y - a2.y + b.y;  hi.y = a1.y + a2.y + b.y;
        lo.z = a1.z - a2.z + b.z;  hi.z = a1.z + a2.z + b.z;
        lo.w = a1.w - a2.w + b.w;  hi.w = a1.w + a2.w + b.w;
        reinterpret_cast<float4*>(out)[col4] = lo;              // bound_l
        reinterpret_cast<float4*>(out + OUT_DIM)[col4] = hi;    // bound_u
    }
}

extern "C" void kernel_launch(void* const* d_in, const int* in_sizes, int n_in,
                              void* d_out, int out_size) {
    const float* l    = (const float*)d_in[0];
    const float* u    = (const float*)d_in[1];
    const float* w    = (const float*)d_in[2];
    const float* bias = (const float*)d_in[3];
    float* out = (float*)d_out;

    dim3 grid(N_STRIPES, N_ROW_CHUNKS);   // (32, 32) = 1024 CTAs
    ibp_partial_kernel<<<grid, P_THREADS>>>(l, u, w);
    ibp_reduce_kernel<<<(OUT_DIM / 4) / R_COLS4, R_THREADS>>>(bias, out);  // 256 CTAs
}

// round 7
// speedup vs baseline: 1.0794x; 1.0794x over previous
#include <cuda_runtime.h>

// Problem constants
#define IN_DIM  8192
#define OUT_DIM 8192

// Partial-kernel tiling: 128 threads x float2 = 256 cols/block
#define P_THREADS 128
#define VEC 2
#define COLS_PER_BLOCK (P_THREADS * VEC)            // 256
#define N_STRIPES      (OUT_DIM / COLS_PER_BLOCK)   // 32
#define N_ROW_CHUNKS   64
#define ROWS_PER_CHUNK (IN_DIM / N_ROW_CHUNKS)      // 128

// Scratch for partial sums: [chunk][col]  (4 MB total)
__device__ float g_s1[N_ROW_CHUNKS * OUT_DIM];
__device__ float g_s2[N_ROW_CHUNKS * OUT_DIM];

__global__ __launch_bounds__(P_THREADS)
void ibp_partial_kernel(const float* __restrict__ l,
                        const float* __restrict__ u,
                        const float* __restrict__ w) {
    __shared__ float sc[ROWS_PER_CHUNK];
    __shared__ float sr[ROWS_PER_CHUNK];

    const int col0 = blockIdx.x * COLS_PER_BLOCK + threadIdx.x * VEC;
    const int row0 = blockIdx.y * ROWS_PER_CHUNK;

    for (int i = threadIdx.x; i < ROWS_PER_CHUNK; i += P_THREADS) {
        float lv = l[row0 + i];
        float uv = u[row0 + i];
        sc[i] = 0.5f * (lv + uv);
        sr[i] = 0.5f * (uv - lv);
    }
    __syncthreads();

    float s1x = 0.f, s1y = 0.f;
    float s2x = 0.f, s2y = 0.f;

    const float2* __restrict__ wp =
        reinterpret_cast<const float2*>(w + (size_t)row0 * OUT_DIM + col0);
    const size_t rstride = OUT_DIM / 2;

    #pragma unroll 16
    for (int i = 0; i < ROWS_PER_CHUNK; i++) {
        float2 wv = __ldcs(&wp[(size_t)i * rstride]);   // stream, evict-first
        float c = sc[i];
        float r = sr[i];
        s1x = fmaf(c, wv.x, s1x);
        s1y = fmaf(c, wv.y, s1y);
        s2x = fmaf(r, fabsf(wv.x), s2x);
        s2y = fmaf(r, fabsf(wv.y), s2y);
    }

    const size_t base = (size_t)blockIdx.y * OUT_DIM + col0;
    *reinterpret_cast<float2*>(&g_s1[base]) = make_float2(s1x, s1y);
    *reinterpret_cast<float2*>(&g_s2[base]) = make_float2(s2x, s2y);
}

// Reduce (identical to R4 best): grid 256 blocks x 256 threads.
// Block covers 8 float4-cols x 32 groups; each group sums 2 chunks;
// smem tree-reduce 32 -> 1 across groups.
#define R_THREADS 256
#define R_COLS4   8                                   // float4 cols per block
#define R_GROUPS  32
#define R_CHUNKS_PER_GROUP (N_ROW_CHUNKS / R_GROUPS)  // 2

__global__ __launch_bounds__(R_THREADS)
void ibp_reduce_kernel(const float* __restrict__ bias,
                       float* __restrict__ out) {
    __shared__ float4 sm1[R_GROUPS][R_COLS4];
    __shared__ float4 sm2[R_GROUPS][R_COLS4];

    const int tx  = threadIdx.x & (R_COLS4 - 1);   // float4 col within block
    const int grp = threadIdx.x / R_COLS4;         // chunk group (0..31)
    const int col4 = blockIdx.x * R_COLS4 + tx;    // float4 index in [0, 2048)

    const float4* p1 = reinterpret_cast<const float4*>(g_s1);
    const float4* p2 = reinterpret_cast<const float4*>(g_s2);
    const size_t cstride = OUT_DIM / 4;            // float4 stride per chunk

    float4 a1 = make_float4(0.f, 0.f, 0.f, 0.f);
    float4 a2 = make_float4(0.f, 0.f, 0.f, 0.f);
    #pragma unroll
    for (int i = 0; i < R_CHUNKS_PER_GROUP; i++) {
        int c = grp * R_CHUNKS_PER_GROUP + i;
        float4 v1 = p1[(size_t)c * cstride + col4];
        float4 v2 = p2[(size_t)c * cstride + col4];
        a1.x += v1.x; a1.y += v1.y; a1.z += v1.z; a1.w += v1.w;
        a2.x += v2.x; a2.y += v2.y; a2.z += v2.z; a2.w += v2.w;
    }
    sm1[grp][tx] = a1;
    sm2[grp][tx] = a2;
    __syncthreads();

    #pragma unroll
    for (int s = R_GROUPS / 2; s >= 1; s >>= 1) {
        if (grp < s) {
            float4 b1 = sm1[grp + s][tx];
            float4 b2 = sm2[grp + s][tx];
            a1.x += b1.x; a1.y += b1.y; a1.z += b1.z; a1.w += b1.w;
            a2.x += b2.x; a2.y += b2.y; a2.z += b2.z; a2.w += b2.w;
            sm1[grp][tx] = a1;
            sm2[grp][tx] = a2;
        }
        __syncthreads();
    }

    if (grp == 0) {
        float4 b = reinterpret_cast<const float4*>(bias)[col4];
        float4 lo, hi;
        lo.x = a1.x - a2.x + b.x;  hi.x = a1.x + a2.x + b.x;
        lo.y = a1.y - a2.y + b.y;  hi.y = a1.y + a2.y + b.y;
        lo.z = a1.z - a2.z + b.z;  hi.z = a1.z + a2.z + b.z;
        lo.w = a1.w - a2.w + b.w;  hi.w = a1.w + a2.w + b.w;
        reinterpret_cast<float4*>(out)[col4] = lo;              // bound_l
        reinterpret_cast<float4*>(out + OUT_DIM)[col4] = hi;    // bound_u
    }
}

extern "C" void kernel_launch(void* const* d_in, const int* in_sizes, int n_in,
                              void* d_out, int out_size) {
    const float* l    = (const float*)d_in[0];
    const float* u    = (const float*)d_in[1];
    const float* w    = (const float*)d_in[2];
    const float* bias = (const float*)d_in[3];
    float* out = (float*)d_out;

    dim3 grid(N_STRIPES, N_ROW_CHUNKS);   // (32, 64) = 2048 CTAs
    ibp_partial_kernel<<<grid, P_THREADS>>>(l, u, w);
    ibp_reduce_kernel<<<(OUT_DIM / 4) / R_COLS4, R_THREADS>>>(bias, out);  // 256 CTAs
}

// round 8
// speedup vs baseline: 1.1310x; 1.0478x over previous
#include <cuda_runtime.h>

// Problem constants
#define IN_DIM  8192
#define OUT_DIM 8192

// Partial-kernel tiling: 128 threads x float2 = 256 cols/block, 64 row chunks
#define P_THREADS 128
#define VEC 2
#define COLS_PER_BLOCK (P_THREADS * VEC)            // 256
#define N_STRIPES      (OUT_DIM / COLS_PER_BLOCK)   // 32
#define N_ROW_CHUNKS   64
#define ROWS_PER_CHUNK (IN_DIM / N_ROW_CHUNKS)      // 128

// Init: seed both output halves with bias (out is poisoned each replay)
#define I_THREADS 256
__global__ __launch_bounds__(I_THREADS)
void ibp_init_kernel(const float* __restrict__ bias,
                     float* __restrict__ out) {
    const int i = blockIdx.x * I_THREADS + threadIdx.x;   // [0, 2048) float4s
    float4 b = reinterpret_cast<const float4*>(bias)[i];
    reinterpret_cast<float4*>(out)[i] = b;                // bound_l base
    reinterpret_cast<float4*>(out + OUT_DIM)[i] = b;      // bound_u base
}

__device__ __forceinline__ void red_add_v2(float* p, float x, float y) {
    asm volatile("red.global.add.v2.f32 [%0], {%1, %2};"
                 :: "l"(p), "f"(x), "f"(y) : "memory");
}

__global__ __launch_bounds__(P_THREADS)
void ibp_partial_kernel(const float* __restrict__ l,
                        const float* __restrict__ u,
                        const float* __restrict__ w,
                        float* __restrict__ out) {
    __shared__ float sc[ROWS_PER_CHUNK];
    __shared__ float sr[ROWS_PER_CHUNK];

    const int col0 = blockIdx.x * COLS_PER_BLOCK + threadIdx.x * VEC;
    const int row0 = blockIdx.y * ROWS_PER_CHUNK;

    for (int i = threadIdx.x; i < ROWS_PER_CHUNK; i += P_THREADS) {
        float lv = l[row0 + i];
        float uv = u[row0 + i];
        sc[i] = 0.5f * (lv + uv);
        sr[i] = 0.5f * (uv - lv);
    }
    __syncthreads();

    float s1x = 0.f, s1y = 0.f;
    float s2x = 0.f, s2y = 0.f;

    const float2* __restrict__ wp =
        reinterpret_cast<const float2*>(w + (size_t)row0 * OUT_DIM + col0);
    const size_t rstride = OUT_DIM / 2;

    #pragma unroll 16
    for (int i = 0; i < ROWS_PER_CHUNK; i++) {
        float2 wv = __ldcs(&wp[(size_t)i * rstride]);   // stream, evict-first
        float c = sc[i];
        float r = sr[i];
        s1x = fmaf(c, wv.x, s1x);
        s1y = fmaf(c, wv.y, s1y);
        s2x = fmaf(r, fabsf(wv.x), s2x);
        s2y = fmaf(r, fabsf(wv.y), s2y);
    }

    // Accumulate directly into the (bias-seeded, L2-resident) outputs.
    red_add_v2(out + col0,           s1x - s2x, s1y - s2y);   // bound_l
    red_add_v2(out + OUT_DIM + col0, s1x + s2x, s1y + s2y);   // bound_u
}

extern "C" void kernel_launch(void* const* d_in, const int* in_sizes, int n_in,
                              void* d_out, int out_size) {
    const float* l    = (const float*)d_in[0];
    const float* u    = (const float*)d_in[1];
    const float* w    = (const float*)d_in[2];
    const float* bias = (const float*)d_in[3];
    float* out = (float*)d_out;

    ibp_init_kernel<<<(OUT_DIM / 4) / I_THREADS, I_THREADS>>>(bias, out);  // 8 CTAs
    dim3 grid(N_STRIPES, N_ROW_CHUNKS);   // (32, 64) = 2048 CTAs
    ibp_partial_kernel<<<grid, P_THREADS>>>(l, u, w, out);
}